// round 1
// baseline (speedup 1.0000x reference)
#include <cuda_runtime.h>
#include <math_constants.h>

#define NB   16
#define NP   4096
#define SS   1024
#define KK   64
#define CIN  64
#define NC   (NB*SS)   /* 16384 centers */

// ---------------- scratch (static device globals; no allocation) ----------------
__device__ int g_fps[NC];
__device__ int g_nbr[NC*KK];
__device__ int g_cnt[NC];

// Reference-matching squared distance: no FMA contraction, sum order (x+y)+z.
__device__ __forceinline__ float d2_ref(float dx, float dy, float dz) {
    return __fadd_rn(__fadd_rn(__fmul_rn(dx,dx), __fmul_rn(dy,dy)), __fmul_rn(dz,dz));
}

// =====================================================================
// Kernel 1: farthest point sampling. One block per cloud, 512 threads,
// 8 points per thread held entirely in registers (pos + dmin).
// =====================================================================
__global__ __launch_bounds__(512) void fps_kernel(const float* __restrict__ pos)
{
    const int b = blockIdx.x;
    const float* p = pos + (size_t)b * NP * 3;
    const int tid = threadIdx.x;
    const int i0 = tid * 8;

    float px[8], py[8], pz[8], dmin[8];
    #pragma unroll
    for (int j = 0; j < 8; j++) {
        px[j] = p[3*(i0+j)+0];
        py[j] = p[3*(i0+j)+1];
        pz[j] = p[3*(i0+j)+2];
        dmin[j] = CUDART_INF_F;
    }

    __shared__ float rv[16];
    __shared__ int   ri[16];
    __shared__ int   scur;
    if (tid == 0) { g_fps[b*SS] = 0; scur = 0; }
    __syncthreads();

    int cur = 0;
    for (int t = 1; t < SS; t++) {
        // broadcast current farthest point (L1-hit, same address all lanes)
        float cx = p[3*cur], cy = p[3*cur+1], cz = p[3*cur+2];

        float bv = -1.0f; int bi = NP;
        #pragma unroll
        for (int j = 0; j < 8; j++) {
            float d  = d2_ref(px[j]-cx, py[j]-cy, pz[j]-cz);
            float dm = fminf(dmin[j], d);
            dmin[j] = dm;
            if (dm > bv) { bv = dm; bi = i0 + j; }   // strict > keeps first index
        }
        // warp reduce (max value, min index on tie)
        #pragma unroll
        for (int o = 16; o > 0; o >>= 1) {
            float v2 = __shfl_down_sync(0xffffffffu, bv, o);
            int   i2 = __shfl_down_sync(0xffffffffu, bi, o);
            if (v2 > bv || (v2 == bv && i2 < bi)) { bv = v2; bi = i2; }
        }
        if ((tid & 31) == 0) { rv[tid >> 5] = bv; ri[tid >> 5] = bi; }
        __syncthreads();
        if (tid < 32) {
            float v = (tid < 16) ? rv[tid] : -1.0f;
            int   i = (tid < 16) ? ri[tid] : NP;
            #pragma unroll
            for (int o = 8; o > 0; o >>= 1) {
                float v2 = __shfl_down_sync(0xffffffffu, v, o);
                int   i2 = __shfl_down_sync(0xffffffffu, i, o);
                if (v2 > v || (v2 == v && i2 < i)) { v = v2; i = i2; }
            }
            if (tid == 0) { scur = i; g_fps[b*SS + t] = i; }
        }
        __syncthreads();
        cur = scur;
    }
}

// =====================================================================
// Kernel 2: ball query, exact K-nearest within radius.
// One warp per center; candidates buffered then bitonic-sorted
// on packed (d2_bits<<32 | idx) for stable, exact selection.
// =====================================================================
__global__ __launch_bounds__(128) void ballq_kernel(const float* __restrict__ pos)
{
    __shared__ unsigned long long buf[4][512];
    __shared__ int scnt[4];

    const int w    = threadIdx.x >> 5;
    const int lane = threadIdx.x & 31;
    const int g    = blockIdx.x * 4 + w;
    const int b    = g >> 10;
    const float* p = pos + (size_t)b * NP * 3;

    const int ci = g_fps[g];
    const float cx = p[3*ci], cy = p[3*ci+1], cz = p[3*ci+2];

    if (lane == 0) scnt[w] = 0;
    __syncwarp();

    for (int i = lane; i < NP; i += 32) {
        float d = d2_ref(cx - p[3*i], cy - p[3*i+1], cz - p[3*i+2]);
        if (d <= 0.04f) {
            int pp = atomicAdd(&scnt[w], 1);
            if (pp < 512)
                buf[w][pp] = ((unsigned long long)__float_as_uint(d) << 32) | (unsigned)i;
        }
    }
    __syncwarp();
    const int m = min(scnt[w], 512);
    for (int i = m + lane; i < 512; i += 32) buf[w][i] = ~0ull;
    __syncwarp();

    // bitonic sort ascending, 512 elems, 1 warp
    for (int k = 2; k <= 512; k <<= 1) {
        for (int j = k >> 1; j > 0; j >>= 1) {
            for (int i = lane; i < 512; i += 32) {
                int ixj = i ^ j;
                if (ixj > i) {
                    unsigned long long a = buf[w][i], c = buf[w][ixj];
                    bool up = ((i & k) == 0);
                    if ((a > c) == up) { buf[w][i] = c; buf[w][ixj] = a; }
                }
            }
            __syncwarp();
        }
    }

    const int n = min(m, KK);
    if (lane == 0) g_cnt[g] = n;
    for (int t = lane; t < KK; t += 32) {
        unsigned long long e = buf[w][(t < n) ? t : 0];  // pad with nearest (= center itself)
        g_nbr[g*KK + t] = (int)(e & 0xffffffffu);
    }
}

// =====================================================================
// Kernel 3: fused MLP + masked max aggregation.
// One block (128 threads) per center. fp32, 4x8 register tiles.
// Shared: A[64x69] (features / H2), H[64x69] (H1 / reduce buffer),
//         Wt[32x64] weight chunk, bias[64].  ~43.8 KB static.
// =====================================================================
#define ASTR 69

__device__ __forceinline__ void mm_phase(
    const float* __restrict__ src, int KD,
    const float* __restrict__ Wg, int ldw, int colofs,
    const float* __restrict__ bg,
    float* Wt, float* bias, float acc[4][8],
    int r0, int c0, int tid)
{
    for (int i = tid; i < 64; i += 128) bias[i] = bg[colofs + i];
    __syncthreads();
    #pragma unroll
    for (int j = 0; j < 4; j++)
        #pragma unroll
        for (int i = 0; i < 8; i++) acc[j][i] = bias[c0 + i];

    for (int k0 = 0; k0 < KD; k0 += 32) {
        const int kc = min(32, KD - k0);
        __syncthreads();
        for (int t = tid; t < kc * 64; t += 128)
            Wt[t] = Wg[(size_t)(k0 + (t >> 6)) * ldw + colofs + (t & 63)];
        __syncthreads();
        for (int k = 0; k < kc; k++) {
            float4 w0 = *(const float4*)&Wt[(k << 6) + c0];
            float4 w1 = *(const float4*)&Wt[(k << 6) + c0 + 4];
            #pragma unroll
            for (int j = 0; j < 4; j++) {
                float f = src[(r0 + j) * ASTR + k0 + k];
                acc[j][0] = fmaf(f, w0.x, acc[j][0]);
                acc[j][1] = fmaf(f, w0.y, acc[j][1]);
                acc[j][2] = fmaf(f, w0.z, acc[j][2]);
                acc[j][3] = fmaf(f, w0.w, acc[j][3]);
                acc[j][4] = fmaf(f, w1.x, acc[j][4]);
                acc[j][5] = fmaf(f, w1.y, acc[j][5]);
                acc[j][6] = fmaf(f, w1.z, acc[j][6]);
                acc[j][7] = fmaf(f, w1.w, acc[j][7]);
            }
        }
    }
    __syncthreads();
}

__global__ __launch_bounds__(128) void mlp_kernel(
    const float* __restrict__ x, const float* __restrict__ pos,
    const float* __restrict__ W1, const float* __restrict__ b1,
    const float* __restrict__ W2, const float* __restrict__ b2,
    const float* __restrict__ W3, const float* __restrict__ b3,
    float* __restrict__ out)
{
    __shared__ float A[64 * ASTR];
    __shared__ float H[64 * ASTR];
    __shared__ float Wt[32 * 64];
    __shared__ float bias[64];

    const int g = blockIdx.x;
    const int b = g >> 10;
    const int tid = threadIdx.x;
    const int n = g_cnt[g];
    const float* p = pos + (size_t)b * NP * 3;
    const int ci = g_fps[g];
    const float cx = p[3*ci], cy = p[3*ci+1], cz = p[3*ci+2];

    // gather features: rows = neighbors, cols 0..63 = x_j, 64..66 = rel pos
    {
        const int r = tid >> 1, half = tid & 1;
        const int idx = g_nbr[g*KK + r];
        const bool v = r < n;
        const float4* xr4 = (const float4*)(x + ((size_t)(b*NP + idx)) * CIN);
        #pragma unroll
        for (int q = 0; q < 8; q++) {
            float4 vv = v ? xr4[half*8 + q] : make_float4(0.f,0.f,0.f,0.f);
            float* dst = &A[r*ASTR + half*32 + 4*q];
            dst[0] = vv.x; dst[1] = vv.y; dst[2] = vv.z; dst[3] = vv.w;
        }
        if (half == 0) {
            A[r*ASTR + 64] = v ? (p[3*idx+0] - cx) : 0.f;
            A[r*ASTR + 65] = v ? (p[3*idx+1] - cy) : 0.f;
            A[r*ASTR + 66] = v ? (p[3*idx+2] - cz) : 0.f;
        }
    }
    __syncthreads();

    const int rg = tid >> 3;
    const int r0 = rg << 2;
    const int c0 = (tid & 7) << 3;
    float acc[4][8];

    // layer 1: relu(A[64x67] @ W1[67x64] + b1) -> H
    mm_phase(A, 67, W1, 64, 0, b1, Wt, bias, acc, r0, c0, tid);
    #pragma unroll
    for (int j = 0; j < 4; j++)
        #pragma unroll
        for (int i = 0; i < 8; i++)
            H[(r0+j)*ASTR + c0 + i] = fmaxf(acc[j][i], 0.f);

    // layer 2: relu(H[64x64] @ W2[64x64] + b2) -> A
    mm_phase(H, 64, W2, 64, 0, b2, Wt, bias, acc, r0, c0, tid);
    #pragma unroll
    for (int j = 0; j < 4; j++)
        #pragma unroll
        for (int i = 0; i < 8; i++)
            A[(r0+j)*ASTR + c0 + i] = fmaxf(acc[j][i], 0.f);

    // layer 3 in two column halves: A[64x64] @ W3[64x128] + b3, then masked max
    #pragma unroll
    for (int hh = 0; hh < 2; hh++) {
        mm_phase(A, 64, W3, 128, hh * 64, b3, Wt, bias, acc, r0, c0, tid);
        // per-thread reduce over its 4 rows with validity mask
        float m[8];
        #pragma unroll
        for (int i = 0; i < 8; i++) {
            float v = -CUDART_INF_F;
            #pragma unroll
            for (int j = 0; j < 4; j++)
                if (r0 + j < n) v = fmaxf(v, acc[j][i]);
            m[i] = v;
        }
        __syncthreads();
        #pragma unroll
        for (int i = 0; i < 8; i++) H[rg*64 + c0 + i] = m[i];
        __syncthreads();
        if (tid < 64) {
            float v = H[tid];
            for (int q = 1; q < 16; q++) v = fmaxf(v, H[q*64 + tid]);
            out[(size_t)g*128 + hh*64 + tid] = v;
        }
        __syncthreads();
    }
}

// =====================================================================
// Kernel 4: pos_out + batch_out tail (layout-guarded by out_size).
// =====================================================================
__global__ void tail_kernel(const float* __restrict__ pos, float* __restrict__ out,
                            long long out_size)
{
    const int i = blockIdx.x * blockDim.x + threadIdx.x;
    if (i >= NC) return;
    const int b = i >> 10;
    const int ci = g_fps[i];
    const float* p = pos + ((size_t)b * NP + ci) * 3;

    const long long base = (long long)NC * 128;
    if (base + (long long)NC * 3 <= out_size) {
        out[base + i*3 + 0] = p[0];
        out[base + i*3 + 1] = p[1];
        out[base + i*3 + 2] = p[2];
    }
    const long long base2 = base + (long long)NC * 3;
    const long long rem = out_size - base2;
    if (rem >= (long long)NC * 2) {
        // int64 batch stored raw (2 x 32-bit slots per element)
        ((long long*)(out + base2))[i] = (long long)b;
    } else if (rem >= (long long)NC) {
        out[base2 + i] = (float)b;
    }
}

// =====================================================================
extern "C" void kernel_launch(void* const* d_in, const int* in_sizes, int n_in,
                              void* d_out, int out_size)
{
    const float* x   = (const float*)d_in[0];
    const float* pos = (const float*)d_in[1];
    // d_in[2] = batch (unused; layout is fixed B x NP)
    const float* W1 = (const float*)d_in[3];
    const float* b1 = (const float*)d_in[4];
    const float* W2 = (const float*)d_in[5];
    const float* b2 = (const float*)d_in[6];
    const float* W3 = (const float*)d_in[7];
    const float* b3 = (const float*)d_in[8];
    float* out = (float*)d_out;

    fps_kernel<<<NB, 512>>>(pos);
    ballq_kernel<<<NC/4, 128>>>(pos);
    mlp_kernel<<<NC, 128>>>(x, pos, W1, b1, W2, b2, W3, b3, out);
    tail_kernel<<<NC/256, 256>>>(pos, out, (long long)out_size);
}

// round 2
// speedup vs baseline: 1.7609x; 1.7609x over previous
#include <cuda_runtime.h>
#include <cuda_bf16.h>
#include <math_constants.h>

#define NB   16
#define NP   4096
#define SS   1024
#define KK   64
#define CIN  64
#define NC   (NB*SS)   /* 16384 centers */
#define TEAMS 592      /* 148 blocks x 4 teams */

typedef unsigned short ushort_t;
typedef unsigned int   uint_t;

// ---------------- scratch (static device globals; no allocation) ----------------
__device__ int g_fps[NC];
__device__ int g_nbr[NC*KK];
__device__ int g_cnt[NC];

// Reference-matching squared distance: no FMA contraction, sum order (x+y)+z.
__device__ __forceinline__ float d2_ref(float dx, float dy, float dz) {
    return __fadd_rn(__fadd_rn(__fmul_rn(dx,dx), __fmul_rn(dy,dy)), __fmul_rn(dz,dz));
}

// =====================================================================
// Kernel 1: farthest point sampling (exact match to reference argmax).
// =====================================================================
__global__ __launch_bounds__(512) void fps_kernel(const float* __restrict__ pos)
{
    const int b = blockIdx.x;
    const float* p = pos + (size_t)b * NP * 3;
    const int tid = threadIdx.x;
    const int i0 = tid * 8;

    float px[8], py[8], pz[8], dmin[8];
    #pragma unroll
    for (int j = 0; j < 8; j++) {
        px[j] = p[3*(i0+j)+0];
        py[j] = p[3*(i0+j)+1];
        pz[j] = p[3*(i0+j)+2];
        dmin[j] = CUDART_INF_F;
    }

    __shared__ float rv[16];
    __shared__ int   ri[16];
    __shared__ int   scur;
    if (tid == 0) { g_fps[b*SS] = 0; scur = 0; }
    __syncthreads();

    int cur = 0;
    for (int t = 1; t < SS; t++) {
        float cx = p[3*cur], cy = p[3*cur+1], cz = p[3*cur+2];

        float bv = -1.0f; int bi = NP;
        #pragma unroll
        for (int j = 0; j < 8; j++) {
            float d  = d2_ref(px[j]-cx, py[j]-cy, pz[j]-cz);
            float dm = fminf(dmin[j], d);
            dmin[j] = dm;
            if (dm > bv) { bv = dm; bi = i0 + j; }
        }
        #pragma unroll
        for (int o = 16; o > 0; o >>= 1) {
            float v2 = __shfl_down_sync(0xffffffffu, bv, o);
            int   i2 = __shfl_down_sync(0xffffffffu, bi, o);
            if (v2 > bv || (v2 == bv && i2 < bi)) { bv = v2; bi = i2; }
        }
        if ((tid & 31) == 0) { rv[tid >> 5] = bv; ri[tid >> 5] = bi; }
        __syncthreads();
        if (tid < 32) {
            float v = (tid < 16) ? rv[tid] : -1.0f;
            int   i = (tid < 16) ? ri[tid] : NP;
            #pragma unroll
            for (int o = 8; o > 0; o >>= 1) {
                float v2 = __shfl_down_sync(0xffffffffu, v, o);
                int   i2 = __shfl_down_sync(0xffffffffu, i, o);
                if (v2 > v || (v2 == v && i2 < i)) { v = v2; i = i2; }
            }
            if (tid == 0) { scur = i; g_fps[b*SS + t] = i; }
        }
        __syncthreads();
        cur = scur;
    }
}

// =====================================================================
// Kernel 2: ball query, exact K-nearest within radius (cap 256).
// =====================================================================
#define BQCAP 256
__global__ __launch_bounds__(128) void ballq_kernel(const float* __restrict__ pos)
{
    __shared__ unsigned long long buf[4][BQCAP];
    __shared__ int scnt[4];

    const int w    = threadIdx.x >> 5;
    const int lane = threadIdx.x & 31;
    const int g    = blockIdx.x * 4 + w;
    const int b    = g >> 10;
    const float* p = pos + (size_t)b * NP * 3;

    const int ci = g_fps[g];
    const float cx = p[3*ci], cy = p[3*ci+1], cz = p[3*ci+2];

    if (lane == 0) scnt[w] = 0;
    __syncwarp();

    for (int i = lane; i < NP; i += 32) {
        float d = d2_ref(cx - p[3*i], cy - p[3*i+1], cz - p[3*i+2]);
        if (d <= 0.04f) {
            int pp = atomicAdd(&scnt[w], 1);
            if (pp < BQCAP)
                buf[w][pp] = ((unsigned long long)__float_as_uint(d) << 32) | (unsigned)i;
        }
    }
    __syncwarp();
    const int m = min(scnt[w], BQCAP);
    for (int i = m + lane; i < BQCAP; i += 32) buf[w][i] = ~0ull;
    __syncwarp();

    for (int k = 2; k <= BQCAP; k <<= 1) {
        for (int j = k >> 1; j > 0; j >>= 1) {
            for (int i = lane; i < BQCAP; i += 32) {
                int ixj = i ^ j;
                if (ixj > i) {
                    unsigned long long a = buf[w][i], c = buf[w][ixj];
                    bool up = ((i & k) == 0);
                    if ((a > c) == up) { buf[w][i] = c; buf[w][ixj] = a; }
                }
            }
            __syncwarp();
        }
    }

    const int n = min(m, KK);
    if (lane == 0) g_cnt[g] = n;
    for (int t = lane; t < KK; t += 32) {
        unsigned long long e = buf[w][(t < n) ? t : 0];
        g_nbr[g*KK + t] = (int)(e & 0xffffffffu);
    }
}

// =====================================================================
// Kernel 3: tensor-core MLP + masked max (bf16 hi/lo split, fp32 acc).
// =====================================================================
__device__ __forceinline__ void split2(float v, ushort_t& h, ushort_t& l) {
    __nv_bfloat16 hb = __float2bfloat16(v);
    float hf = __bfloat162float(hb);
    __nv_bfloat16 lb = __float2bfloat16(v - hf);
    h = __bfloat16_as_ushort(hb);
    l = __bfloat16_as_ushort(lb);
}
__device__ __forceinline__ void pack_store(ushort_t* ph, ushort_t* pl, int off, float a, float b) {
    ushort_t h0,l0,h1,l1; split2(a,h0,l0); split2(b,h1,l1);
    *(uint_t*)(ph+off) = (uint_t)h0 | ((uint_t)h1<<16);
    *(uint_t*)(pl+off) = (uint_t)l0 | ((uint_t)l1<<16);
}
__device__ __forceinline__ void mma16816(float* c, uint_t a0,uint_t a1,uint_t a2,uint_t a3,
                                         uint_t b0, uint_t b1) {
    asm volatile("mma.sync.aligned.m16n8k16.row.col.f32.bf16.bf16.f32 "
        "{%0,%1,%2,%3}, {%4,%5,%6,%7}, {%8,%9}, {%0,%1,%2,%3};"
        : "+f"(c[0]),"+f"(c[1]),"+f"(c[2]),"+f"(c[3])
        : "r"(a0),"r"(a1),"r"(a2),"r"(a3),"r"(b0),"r"(b1));
}

// One GEMM layer slice: 16 rows (this warp) x 64 cols, K = KS*16.
template<int KS>
__device__ __forceinline__ void mm_layer(
    const ushort_t* __restrict__ ah, const ushort_t* __restrict__ al,
    const ushort_t* __restrict__ wh, const ushort_t* __restrict__ wl, int wstr,
    const float* __restrict__ bs,
    float acc[8][4], int g4, int tig, int r0)
{
    #pragma unroll
    for (int nt = 0; nt < 8; nt++) {
        int c0 = nt*8 + tig*2;
        acc[nt][0] = bs[c0]; acc[nt][1] = bs[c0+1];
        acc[nt][2] = acc[nt][0]; acc[nt][3] = acc[nt][1];
    }
    #pragma unroll
    for (int ks = 0; ks < KS; ks++) {
        const int kofs = ks*16 + tig*2;
        const ushort_t* arh = ah + (r0+g4)*88 + kofs;
        const ushort_t* arl = al + (r0+g4)*88 + kofs;
        uint_t Ah0 = *(const uint_t*)(arh);
        uint_t Ah1 = *(const uint_t*)(arh + 8*88);
        uint_t Ah2 = *(const uint_t*)(arh + 8);
        uint_t Ah3 = *(const uint_t*)(arh + 8*88 + 8);
        uint_t Al0 = *(const uint_t*)(arl);
        uint_t Al1 = *(const uint_t*)(arl + 8*88);
        uint_t Al2 = *(const uint_t*)(arl + 8);
        uint_t Al3 = *(const uint_t*)(arl + 8*88 + 8);
        #pragma unroll
        for (int nt = 0; nt < 8; nt++) {
            const ushort_t* wrh = wh + (nt*8+g4)*wstr + kofs;
            const ushort_t* wrl = wl + (nt*8+g4)*wstr + kofs;
            uint_t Bh0 = *(const uint_t*)(wrh);
            uint_t Bh1 = *(const uint_t*)(wrh + 8);
            uint_t Bl0 = *(const uint_t*)(wrl);
            uint_t Bl1 = *(const uint_t*)(wrl + 8);
            mma16816(acc[nt], Ah0,Ah1,Ah2,Ah3, Bh0,Bh1);
            mma16816(acc[nt], Ah0,Ah1,Ah2,Ah3, Bl0,Bl1);
            mma16816(acc[nt], Al0,Al1,Al2,Al3, Bh0,Bh1);
        }
    }
}

// smem byte offsets
#define OFS_W1H 0
#define OFS_W1L 11264
#define OFS_W2H 22528
#define OFS_W2L 31744
#define OFS_W3H 40960
#define OFS_W3L 59392
#define OFS_BS  77824
#define OFS_AH  78848
#define OFS_AL  123904
#define OFS_RED 168960
#define SMEM_TOTAL 173056

__global__ __launch_bounds__(512) void mlp_mma_kernel(
    const float* __restrict__ x, const float* __restrict__ pos,
    const float* __restrict__ W1, const float* __restrict__ b1,
    const float* __restrict__ W2, const float* __restrict__ b2,
    const float* __restrict__ W3, const float* __restrict__ b3,
    float* __restrict__ out)
{
    extern __shared__ unsigned char smem[];
    ushort_t* w1h = (ushort_t*)(smem + OFS_W1H);
    ushort_t* w1l = (ushort_t*)(smem + OFS_W1L);
    ushort_t* w2h = (ushort_t*)(smem + OFS_W2H);
    ushort_t* w2l = (ushort_t*)(smem + OFS_W2L);
    ushort_t* w3h = (ushort_t*)(smem + OFS_W3H);
    ushort_t* w3l = (ushort_t*)(smem + OFS_W3L);
    float*    bs  = (float*)(smem + OFS_BS);
    ushort_t* AH  = (ushort_t*)(smem + OFS_AH);
    ushort_t* AL  = (ushort_t*)(smem + OFS_AL);
    float*    RED = (float*)(smem + OFS_RED);

    const int tid = threadIdx.x;

    // ---- load + split + transpose weights (once per block) ----
    for (int i = tid; i < 64*88; i += 512) {
        int n = i / 88, k = i % 88;
        float v = (k < 67) ? W1[k*64 + n] : 0.f;
        split2(v, w1h[i], w1l[i]);
    }
    for (int i = tid; i < 64*72; i += 512) {
        int n = i / 72, k = i % 72;
        float v = (k < 64) ? W2[k*64 + n] : 0.f;
        split2(v, w2h[i], w2l[i]);
    }
    for (int i = tid; i < 128*72; i += 512) {
        int n = i / 72, k = i % 72;
        float v = (k < 64) ? W3[k*128 + n] : 0.f;
        split2(v, w3h[i], w3l[i]);
    }
    if (tid < 64)  { bs[tid] = b1[tid]; bs[64+tid] = b2[tid]; }
    if (tid < 128) { bs[128+tid] = b3[tid]; }
    __syncthreads();

    const int team  = tid >> 7;          // 0..3
    const int t     = tid & 127;
    const int wteam = t >> 5;            // warp in team
    const int lane  = tid & 31;
    const int g4    = lane >> 2;
    const int tig   = lane & 3;
    const int r0    = wteam * 16;
    ushort_t* ah = AH + team * (64*88);
    ushort_t* al = AL + team * (64*88);
    float*  tred = RED + team * 256;
    const int barid = team + 1;
    const int gteam = blockIdx.x * 4 + team;

    for (int g = gteam; g < NC; g += TEAMS) {
        const int b = g >> 10;
        const float* p = pos + (size_t)b * NP * 3;
        const int ci = g_fps[g];
        const float cx = p[3*ci], cy = p[3*ci+1], cz = p[3*ci+2];
        const int ncnt = g_cnt[g];

        // ---- gather neighbor rows into split-bf16 A ----
        {
            const int r = t >> 1, half = t & 1;
            const int idx = g_nbr[g*KK + r];
            const float4* xr = (const float4*)(x + ((size_t)(b*NP + idx)) * CIN);
            ushort_t* arh = ah + r*88;
            ushort_t* arl = al + r*88;
            #pragma unroll
            for (int q = 0; q < 8; q++) {
                float4 v = xr[half*8 + q];
                int c = half*32 + 4*q;
                pack_store(arh, arl, c,   v.x, v.y);
                pack_store(arh, arl, c+2, v.z, v.w);
            }
            if (half == 0) {
                float rx = p[3*idx]-cx, ry = p[3*idx+1]-cy, rz = p[3*idx+2]-cz;
                pack_store(arh, arl, 64, rx, ry);
                pack_store(arh, arl, 66, rz, 0.f);
                pack_store(arh, arl, 68, 0.f, 0.f);
                pack_store(arh, arl, 70, 0.f, 0.f);
            } else {
                pack_store(arh, arl, 72, 0.f, 0.f);
                pack_store(arh, arl, 74, 0.f, 0.f);
                pack_store(arh, arl, 76, 0.f, 0.f);
                pack_store(arh, arl, 78, 0.f, 0.f);
            }
        }
        asm volatile("bar.sync %0, %1;" :: "r"(barid), "r"(128));

        float acc[8][4];

        // ---- layer 1 ----
        mm_layer<5>(ah, al, w1h, w1l, 88, bs, acc, g4, tig, r0);
        asm volatile("bar.sync %0, %1;" :: "r"(barid), "r"(128));
        #pragma unroll
        for (int nt = 0; nt < 8; nt++) {
            int c0 = nt*8 + tig*2;
            pack_store(ah, al, (r0+g4)*88   + c0, fmaxf(acc[nt][0],0.f), fmaxf(acc[nt][1],0.f));
            pack_store(ah, al, (r0+g4+8)*88 + c0, fmaxf(acc[nt][2],0.f), fmaxf(acc[nt][3],0.f));
        }
        asm volatile("bar.sync %0, %1;" :: "r"(barid), "r"(128));

        // ---- layer 2 ----
        mm_layer<4>(ah, al, w2h, w2l, 72, bs+64, acc, g4, tig, r0);
        asm volatile("bar.sync %0, %1;" :: "r"(barid), "r"(128));
        #pragma unroll
        for (int nt = 0; nt < 8; nt++) {
            int c0 = nt*8 + tig*2;
            pack_store(ah, al, (r0+g4)*88   + c0, fmaxf(acc[nt][0],0.f), fmaxf(acc[nt][1],0.f));
            pack_store(ah, al, (r0+g4+8)*88 + c0, fmaxf(acc[nt][2],0.f), fmaxf(acc[nt][3],0.f));
        }
        asm volatile("bar.sync %0, %1;" :: "r"(barid), "r"(128));

        // ---- layer 3 (two 64-col halves) + masked max ----
        const bool v0 = (r0+g4)   < ncnt;
        const bool v1 = (r0+g4+8) < ncnt;
        #pragma unroll
        for (int h = 0; h < 2; h++) {
            mm_layer<4>(ah, al, w3h + h*64*72, w3l + h*64*72, 72, bs+128+h*64,
                        acc, g4, tig, r0);
            #pragma unroll
            for (int nt = 0; nt < 8; nt++) {
                float m0 = fmaxf(v0 ? acc[nt][0] : -CUDART_INF_F,
                                 v1 ? acc[nt][2] : -CUDART_INF_F);
                float m1 = fmaxf(v0 ? acc[nt][1] : -CUDART_INF_F,
                                 v1 ? acc[nt][3] : -CUDART_INF_F);
                #pragma unroll
                for (int off = 4; off < 32; off <<= 1) {
                    m0 = fmaxf(m0, __shfl_xor_sync(0xffffffffu, m0, off));
                    m1 = fmaxf(m1, __shfl_xor_sync(0xffffffffu, m1, off));
                }
                if (lane < 4) {
                    tred[wteam*64 + nt*8 + lane*2    ] = m0;
                    tred[wteam*64 + nt*8 + lane*2 + 1] = m1;
                }
            }
            asm volatile("bar.sync %0, %1;" :: "r"(barid), "r"(128));
            if (t < 64) {
                float m = fmaxf(fmaxf(tred[t], tred[64+t]),
                                fmaxf(tred[128+t], tred[192+t]));
                out[(size_t)g*128 + h*64 + t] = m;
            }
            asm volatile("bar.sync %0, %1;" :: "r"(barid), "r"(128));
        }
    }
}

// =====================================================================
// Kernel 4: pos_out + batch_out tail.
// =====================================================================
__global__ void tail_kernel(const float* __restrict__ pos, float* __restrict__ out,
                            long long out_size)
{
    const int i = blockIdx.x * blockDim.x + threadIdx.x;
    if (i >= NC) return;
    const int b = i >> 10;
    const int ci = g_fps[i];
    const float* p = pos + ((size_t)b * NP + ci) * 3;

    const long long base = (long long)NC * 128;
    if (base + (long long)NC * 3 <= out_size) {
        out[base + i*3 + 0] = p[0];
        out[base + i*3 + 1] = p[1];
        out[base + i*3 + 2] = p[2];
    }
    const long long base2 = base + (long long)NC * 3;
    const long long rem = out_size - base2;
    if (rem >= (long long)NC * 2) {
        ((long long*)(out + base2))[i] = (long long)b;
    } else if (rem >= (long long)NC) {
        out[base2 + i] = (float)b;
    }
}

// =====================================================================
extern "C" void kernel_launch(void* const* d_in, const int* in_sizes, int n_in,
                              void* d_out, int out_size)
{
    const float* x   = (const float*)d_in[0];
    const float* pos = (const float*)d_in[1];
    const float* W1 = (const float*)d_in[3];
    const float* b1 = (const float*)d_in[4];
    const float* W2 = (const float*)d_in[5];
    const float* b2 = (const float*)d_in[6];
    const float* W3 = (const float*)d_in[7];
    const float* b3 = (const float*)d_in[8];
    float* out = (float*)d_out;

    cudaFuncSetAttribute(mlp_mma_kernel, cudaFuncAttributeMaxDynamicSharedMemorySize, SMEM_TOTAL);

    fps_kernel<<<NB, 512>>>(pos);
    ballq_kernel<<<NC/4, 128>>>(pos);
    mlp_mma_kernel<<<148, 512, SMEM_TOTAL>>>(x, pos, W1, b1, W2, b2, W3, b3, out);
    tail_kernel<<<NC/256, 256>>>(pos, out, (long long)out_size);
}

// round 4
// speedup vs baseline: 1.8122x; 1.0291x over previous
#include <cuda_runtime.h>
#include <cuda_bf16.h>
#include <math_constants.h>

#define NB   16
#define NP   4096
#define SS   1024
#define KK   64
#define CIN  64
#define NC   (NB*SS)   /* 16384 centers */
#define TEAMS 592      /* 148 blocks x 4 teams */

typedef unsigned short ushort_t;
typedef unsigned int   uint_t;

// ---------------- scratch (static device globals; no allocation) ----------------
__device__ int g_fps[NC];
__device__ int g_nbr[NC*KK];
__device__ int g_cnt[NC];
__device__ ushort_t g_xh[(size_t)NB*NP*CIN];   // pre-split x, hi bf16
__device__ ushort_t g_xl[(size_t)NB*NP*CIN];   // pre-split x, lo bf16

// Reference-matching squared distance: no FMA contraction, sum order (x+y)+z.
__device__ __forceinline__ float d2_ref(float dx, float dy, float dz) {
    return __fadd_rn(__fadd_rn(__fmul_rn(dx,dx), __fmul_rn(dy,dy)), __fmul_rn(dz,dz));
}

__device__ __forceinline__ void split_one(float v, ushort_t& h, ushort_t& l) {
    __nv_bfloat16 hb = __float2bfloat16(v);
    __nv_bfloat16 lb = __float2bfloat16(v - __bfloat162float(hb));
    h = __bfloat16_as_ushort(hb); l = __bfloat16_as_ushort(lb);
}
__device__ __forceinline__ void split_pack2(float a, float b, uint_t& h, uint_t& l) {
    ushort_t ha, la, hb, lb;
    split_one(a, ha, la); split_one(b, hb, lb);
    h = (uint_t)ha | ((uint_t)hb << 16);
    l = (uint_t)la | ((uint_t)lb << 16);
}
__device__ __forceinline__ void mma16816(float* c, uint_t a0,uint_t a1,uint_t a2,uint_t a3,
                                         uint_t b0, uint_t b1) {
    asm volatile("mma.sync.aligned.m16n8k16.row.col.f32.bf16.bf16.f32 "
        "{%0,%1,%2,%3}, {%4,%5,%6,%7}, {%8,%9}, {%0,%1,%2,%3};"
        : "+f"(c[0]),"+f"(c[1]),"+f"(c[2]),"+f"(c[3])
        : "r"(a0),"r"(a1),"r"(a2),"r"(a3),"r"(b0),"r"(b1));
}

// =====================================================================
// Kernel 1: blocks 0-15: FPS (exact reference argmax).
//           blocks 16-147: pre-split x -> bf16 hi/lo (overlapped, free).
// =====================================================================
__global__ __launch_bounds__(512) void fps_presplit_kernel(
    const float* __restrict__ pos, const float* __restrict__ x)
{
    const int tid = threadIdx.x;

    if (blockIdx.x >= NB) {
        // ---------------- pre-split x ----------------
        const int N4 = NB*NP*CIN/4;
        const float4* x4 = (const float4*)x;
        uint2* xh2 = (uint2*)g_xh;
        uint2* xl2 = (uint2*)g_xl;
        for (int i = (blockIdx.x - NB)*512 + tid; i < N4; i += 132*512) {
            float4 v = x4[i];
            ushort_t h0,l0,h1,l1,h2,l2,h3,l3;
            split_one(v.x,h0,l0); split_one(v.y,h1,l1);
            split_one(v.z,h2,l2); split_one(v.w,h3,l3);
            xh2[i] = make_uint2((uint_t)h0|((uint_t)h1<<16), (uint_t)h2|((uint_t)h3<<16));
            xl2[i] = make_uint2((uint_t)l0|((uint_t)l1<<16), (uint_t)l2|((uint_t)l3<<16));
        }
        return;
    }

    // ---------------- FPS ----------------
    const int b = blockIdx.x;
    const float* p = pos + (size_t)b * NP * 3;
    const int i0 = tid * 8;

    float px[8], py[8], pz[8], dmin[8];
    #pragma unroll
    for (int j = 0; j < 8; j++) {
        px[j] = p[3*(i0+j)+0];
        py[j] = p[3*(i0+j)+1];
        pz[j] = p[3*(i0+j)+2];
        dmin[j] = CUDART_INF_F;
    }

    __shared__ float rv[16];
    __shared__ int   ri[16];
    __shared__ int   scur;
    if (tid == 0) { g_fps[b*SS] = 0; scur = 0; }
    __syncthreads();

    int cur = 0;
    for (int t = 1; t < SS; t++) {
        float cx = p[3*cur], cy = p[3*cur+1], cz = p[3*cur+2];

        float bv = -1.0f; int bi = NP;
        #pragma unroll
        for (int j = 0; j < 8; j++) {
            float d  = d2_ref(px[j]-cx, py[j]-cy, pz[j]-cz);
            float dm = fminf(dmin[j], d);
            dmin[j] = dm;
            if (dm > bv) { bv = dm; bi = i0 + j; }
        }
        #pragma unroll
        for (int o = 16; o > 0; o >>= 1) {
            float v2 = __shfl_down_sync(0xffffffffu, bv, o);
            int   i2 = __shfl_down_sync(0xffffffffu, bi, o);
            if (v2 > bv || (v2 == bv && i2 < bi)) { bv = v2; bi = i2; }
        }
        if ((tid & 31) == 0) { rv[tid >> 5] = bv; ri[tid >> 5] = bi; }
        __syncthreads();
        if (tid < 32) {
            float v = (tid < 16) ? rv[tid] : -1.0f;
            int   i = (tid < 16) ? ri[tid] : NP;
            #pragma unroll
            for (int o = 8; o > 0; o >>= 1) {
                float v2 = __shfl_down_sync(0xffffffffu, v, o);
                int   i2 = __shfl_down_sync(0xffffffffu, i, o);
                if (v2 > v || (v2 == v && i2 < i)) { v = v2; i = i2; }
            }
            if (tid == 0) { scur = i; g_fps[b*SS + t] = i; }
        }
        __syncthreads();
        cur = scur;
    }
}

// =====================================================================
// Kernel 2: ball query (exact K-nearest within radius; sort only if m>K)
//           + fused pos_out / batch_out tail writes.
// =====================================================================
#define BQCAP 256
__global__ __launch_bounds__(128) void ballq_kernel(const float* __restrict__ pos,
                                                    float* __restrict__ out,
                                                    long long out_size)
{
    __shared__ unsigned long long buf[4][BQCAP];
    __shared__ int scnt[4];

    const int w    = threadIdx.x >> 5;
    const int lane = threadIdx.x & 31;
    const int g    = blockIdx.x * 4 + w;
    const int b    = g >> 10;
    const float* p = pos + (size_t)b * NP * 3;

    const int ci = g_fps[g];
    const float cx = p[3*ci], cy = p[3*ci+1], cz = p[3*ci+2];

    if (lane == 0) scnt[w] = 0;
    __syncwarp();

    for (int i = lane; i < NP; i += 32) {
        float d = d2_ref(cx - p[3*i], cy - p[3*i+1], cz - p[3*i+2]);
        if (d <= 0.04f) {
            int pp = atomicAdd(&scnt[w], 1);
            if (pp < BQCAP)
                buf[w][pp] = ((unsigned long long)__float_as_uint(d) << 32) | (unsigned)i;
        }
    }
    __syncwarp();
    const int m = min(scnt[w], BQCAP);

    if (m > KK) {
        const int n2 = (m <= 128) ? 128 : BQCAP;
        for (int i = m + lane; i < n2; i += 32) buf[w][i] = ~0ull;
        __syncwarp();
        for (int k = 2; k <= n2; k <<= 1) {
            for (int j = k >> 1; j > 0; j >>= 1) {
                for (int i = lane; i < n2; i += 32) {
                    int ixj = i ^ j;
                    if (ixj > i) {
                        unsigned long long a = buf[w][i], c = buf[w][ixj];
                        bool up = ((i & k) == 0);
                        if ((a > c) == up) { buf[w][i] = c; buf[w][ixj] = a; }
                    }
                }
                __syncwarp();
            }
        }
    }
    __syncwarp();

    const int n = min(m, KK);
    if (lane == 0) g_cnt[g] = n;
    for (int t = lane; t < KK; t += 32) {
        unsigned long long e = buf[w][(t < n) ? t : 0];
        g_nbr[g*KK + t] = (int)(e & 0xffffffffu);
    }

    // fused tail: pos_out + batch_out (layout-guarded by out_size)
    if (lane == 0) {
        const long long base = (long long)NC * 128;
        if (base + (long long)NC * 3 <= out_size) {
            out[base + g*3 + 0] = cx;
            out[base + g*3 + 1] = cy;
            out[base + g*3 + 2] = cz;
        }
        const long long base2 = base + (long long)NC * 3;
        const long long rem = out_size - base2;
        if (rem >= (long long)NC * 2) {
            ((long long*)(out + base2))[g] = (long long)b;
        } else if (rem >= (long long)NC) {
            out[base2 + g] = (float)b;
        }
    }
}

// =====================================================================
// Kernel 3: mma.sync MLP with fragment-packed operands.
// 148 persistent blocks x 512 threads = 4 teams/block, 1 center/team-iter.
// All smem operands stored in m16n8k16 fragment order:
//   A slot: [warp][ks][lane] -> uint4 {a0,a1,a2,a3}     (1 LDS.128 / ks)
//   B slot: [slot][lane]     -> uint2 {b0,b1}           (1 LDS.64 / (ks,nt))
// 3-term bf16 hi/lo split, fp32 accumulate (validated rel_err 4.8e-6).
// =====================================================================
// smem byte offsets
#define O_BIAS 0
#define O_BH   1024
#define O_BL   35840
#define O_A1H  70656
#define O_A1L  111616
#define O_A2H  152576
#define O_A2L  185344
#define O_RED  218112
#define SMEM_TOTAL 222208
// B slot bases (in 32-lane slots): L1 = 0 (5ks x 8nt), L2 = 40 (4x8), L3 = 72 (4x16)
#define SLOT_L1 0
#define SLOT_L2 40
#define SLOT_L3 72

template<int KS, int NTL>
__device__ __forceinline__ void mm_packed(
    const unsigned char* sp, int awh, int awl, int slotbase, int ntofs,
    const float* __restrict__ bsl, float acc[8][4], int lane)
{
    const int tig = lane & 3;
    #pragma unroll
    for (int nt = 0; nt < 8; nt++) {
        const int c0 = nt*8 + tig*2;
        acc[nt][0] = bsl[c0]; acc[nt][1] = bsl[c0+1];
        acc[nt][2] = acc[nt][0]; acc[nt][3] = acc[nt][1];
    }
    const uint2* BH = (const uint2*)(sp + O_BH);
    const uint2* BL = (const uint2*)(sp + O_BL);
    #pragma unroll
    for (int ks = 0; ks < KS; ks++) {
        const uint4 Ah = *(const uint4*)(sp + awh + ks*512 + lane*16);
        const uint4 Al = *(const uint4*)(sp + awl + ks*512 + lane*16);
        #pragma unroll
        for (int nt = 0; nt < 8; nt++) {
            const int slot = (slotbase + ks*NTL + ntofs + nt)*32 + lane;
            const uint2 bh = BH[slot];
            const uint2 bl = BL[slot];
            mma16816(acc[nt], Ah.x,Ah.y,Ah.z,Ah.w, bh.x,bh.y);
            mma16816(acc[nt], Ah.x,Ah.y,Ah.z,Ah.w, bl.x,bl.y);
            mma16816(acc[nt], Al.x,Al.y,Al.z,Al.w, bh.x,bh.y);
        }
    }
}

// relu + split + store into packed A2 slot of this warp (8 x STS.128)
__device__ __forceinline__ void epi_relu_pack(
    unsigned char* sp, int a2h, int a2l, float acc[8][4], int lane)
{
    #pragma unroll
    for (int ks = 0; ks < 4; ks++) {
        uint4 H, L;
        split_pack2(fmaxf(acc[2*ks][0],0.f),   fmaxf(acc[2*ks][1],0.f),   H.x, L.x);
        split_pack2(fmaxf(acc[2*ks][2],0.f),   fmaxf(acc[2*ks][3],0.f),   H.y, L.y);
        split_pack2(fmaxf(acc[2*ks+1][0],0.f), fmaxf(acc[2*ks+1][1],0.f), H.z, L.z);
        split_pack2(fmaxf(acc[2*ks+1][2],0.f), fmaxf(acc[2*ks+1][3],0.f), H.w, L.w);
        *(uint4*)(sp + a2h + ks*512 + lane*16) = H;
        *(uint4*)(sp + a2l + ks*512 + lane*16) = L;
    }
}

__global__ __launch_bounds__(512) void mlp_mma_kernel(
    const float* __restrict__ pos,
    const float* __restrict__ W1, const float* __restrict__ b1,
    const float* __restrict__ W2, const float* __restrict__ b2,
    const float* __restrict__ W3, const float* __restrict__ b3,
    float* __restrict__ out)
{
    extern __shared__ unsigned char sp[];
    float* bs = (float*)(sp + O_BIAS);

    const int tid = threadIdx.x;

    // ---- pack weights into fragment order (once per block) ----
    // slot s, lane l: n = nt*8 + (l>>2), k0 = ks*16 + (l&3)*2; values k0,k0+1,k0+8,k0+9
    for (int i = tid; i < 136*32; i += 512) {
        const int s = i >> 5, l = i & 31;
        int ks, nt, layer;
        if (s < 40)      { layer = 1; ks = s >> 3;        nt = s & 7; }
        else if (s < 72) { layer = 2; ks = (s-40) >> 3;   nt = (s-40) & 7; }
        else             { layer = 3; ks = (s-72) >> 4;   nt = (s-72) & 15; }
        const int n  = nt*8 + (l >> 2);
        const int k0 = ks*16 + (l & 3)*2;
        float v[4];
        #pragma unroll
        for (int q = 0; q < 4; q++) {
            const int k = k0 + (q >> 1)*8 + (q & 1);
            if (layer == 1)      v[q] = (k < 67) ? W1[k*64 + n]  : 0.f;
            else if (layer == 2) v[q] = W2[k*64 + n];
            else                 v[q] = W3[k*128 + n];
        }
        uint2 H, L;
        split_pack2(v[0], v[1], H.x, L.x);
        split_pack2(v[2], v[3], H.y, L.y);
        ((uint2*)(sp + O_BH))[i] = H;
        ((uint2*)(sp + O_BL))[i] = L;
    }
    // zero the A1 ks=4 padding block (cols 68..79 stay zero forever)
    for (int i = tid; i < 1024; i += 512) {
        const int team = i >> 8, w = (i >> 6) & 3, hl = (i >> 5) & 1, l = i & 31;
        const int base = (hl ? O_A1L : O_A1H) + team*10240 + w*2560 + 4*512 + l*16;
        *(uint4*)(sp + base) = make_uint4(0,0,0,0);
    }
    if (tid < 64)  { bs[tid] = b1[tid]; bs[64+tid] = b2[tid]; }
    if (tid < 128) { bs[128+tid] = b3[tid]; }
    __syncthreads();

    const int team  = tid >> 7;          // 0..3
    const int t     = tid & 127;
    const int wteam = t >> 5;            // warp in team
    const int lane  = tid & 31;
    const int g4    = lane >> 2;
    const int barid = team + 1;

    const int a1h_t = O_A1H + team*10240;
    const int a1l_t = O_A1L + team*10240;
    const int awh1  = a1h_t + wteam*2560;
    const int awl1  = a1l_t + wteam*2560;
    const int awh2  = O_A2H + team*8192 + wteam*2048;
    const int awl2  = O_A2L + team*8192 + wteam*2048;
    float* tred = (float*)(sp + O_RED) + team*256;

    float acc[8][4];

    for (int g = blockIdx.x*4 + team; g < NC; g += TEAMS) {
        const int b = g >> 10;
        const float* p = pos + (size_t)b * NP * 3;
        const int ci = g_fps[g];
        const int ncnt = g_cnt[g];

        // ---- gather into fragment-packed A1 (pre-split x, no ALU split) ----
        {
            const int r = t >> 1, half = t & 1;
            const int idx = g_nbr[g*KK + r];
            const size_t row = (size_t)(b*NP + idx);
            const uint4* xh4 = (const uint4*)(g_xh + row*CIN);
            const uint4* xl4 = (const uint4*)(g_xl + row*CIN);
            const int dw   = r >> 4;              // destination warp slot
            const int lb   = 4*(r & 7);           // lane base
            const int rhi  = ((r & 15) >= 8) ? 1 : 0;
            const int bh_w = a1h_t + dw*2560;
            const int bl_w = a1l_t + dw*2560;
            #pragma unroll
            for (int q = 0; q < 4; q++) {
                const uint4 vh = xh4[4*half + q];
                const uint4 vl = xl4[4*half + q];
                const int ks  = 2*half + (q >> 1);
                const int reg = ((q & 1) << 1) + rhi;
                const int bh  = bh_w + ks*512 + reg*4;
                const int bl  = bl_w + ks*512 + reg*4;
                *(uint_t*)(sp + bh + (lb+0)*16) = vh.x;
                *(uint_t*)(sp + bh + (lb+1)*16) = vh.y;
                *(uint_t*)(sp + bh + (lb+2)*16) = vh.z;
                *(uint_t*)(sp + bh + (lb+3)*16) = vh.w;
                *(uint_t*)(sp + bl + (lb+0)*16) = vl.x;
                *(uint_t*)(sp + bl + (lb+1)*16) = vl.y;
                *(uint_t*)(sp + bl + (lb+2)*16) = vl.z;
                *(uint_t*)(sp + bl + (lb+3)*16) = vl.w;
            }
            if (half == 0) {
                const float rx = p[3*idx]   - p[3*ci];
                const float ry = p[3*idx+1] - p[3*ci+1];
                const float rz = p[3*idx+2] - p[3*ci+2];
                uint_t h0,l0,h1,l1;
                split_pack2(rx, ry, h0, l0);
                split_pack2(rz, 0.f, h1, l1);
                const int bh = bh_w + 4*512 + rhi*4;
                const int bl = bl_w + 4*512 + rhi*4;
                *(uint_t*)(sp + bh + (lb+0)*16) = h0;
                *(uint_t*)(sp + bh + (lb+1)*16) = h1;
                *(uint_t*)(sp + bl + (lb+0)*16) = l0;
                *(uint_t*)(sp + bl + (lb+1)*16) = l1;
            }
        }
        asm volatile("bar.sync %0, %1;" :: "r"(barid), "r"(128));

        // ---- layer 1: relu(A1 @ W1 + b1) -> A2 (packed) ----
        mm_packed<5,8>(sp, awh1, awl1, SLOT_L1, 0, bs, acc, lane);
        epi_relu_pack(sp, awh2, awl2, acc, lane);
        asm volatile("bar.sync %0, %1;" :: "r"(barid), "r"(128));

        // ---- layer 2: relu(A2 @ W2 + b2) -> A2 (in place) ----
        mm_packed<4,8>(sp, awh2, awl2, SLOT_L2, 0, bs+64, acc, lane);
        asm volatile("bar.sync %0, %1;" :: "r"(barid), "r"(128));
        epi_relu_pack(sp, awh2, awl2, acc, lane);
        asm volatile("bar.sync %0, %1;" :: "r"(barid), "r"(128));

        // ---- layer 3 (two 64-col halves) + masked column max ----
        const bool v0 = g4       < ncnt - wteam*16;   // row r0+g4 valid
        const bool v1 = g4 + 8   < ncnt - wteam*16;   // row r0+g4+8 valid
        #pragma unroll
        for (int h = 0; h < 2; h++) {
            mm_packed<4,16>(sp, awh2, awl2, SLOT_L3, h*8, bs+128+h*64, acc, lane);
            #pragma unroll
            for (int nt = 0; nt < 8; nt++) {
                float m0 = fmaxf(v0 ? acc[nt][0] : -CUDART_INF_F,
                                 v1 ? acc[nt][2] : -CUDART_INF_F);
                float m1 = fmaxf(v0 ? acc[nt][1] : -CUDART_INF_F,
                                 v1 ? acc[nt][3] : -CUDART_INF_F);
                #pragma unroll
                for (int off = 4; off < 32; off <<= 1) {
                    m0 = fmaxf(m0, __shfl_xor_sync(0xffffffffu, m0, off));
                    m1 = fmaxf(m1, __shfl_xor_sync(0xffffffffu, m1, off));
                }
                if (lane < 4) {
                    tred[wteam*64 + nt*8 + lane*2    ] = m0;
                    tred[wteam*64 + nt*8 + lane*2 + 1] = m1;
                }
            }
            asm volatile("bar.sync %0, %1;" :: "r"(barid), "r"(128));
            if (t < 64) {
                float m = fmaxf(fmaxf(tred[t], tred[64+t]),
                                fmaxf(tred[128+t], tred[192+t]));
                out[(size_t)g*128 + h*64 + t] = m;
            }
            asm volatile("bar.sync %0, %1;" :: "r"(barid), "r"(128));
        }
    }
}

// =====================================================================
extern "C" void kernel_launch(void* const* d_in, const int* in_sizes, int n_in,
                              void* d_out, int out_size)
{
    const float* x   = (const float*)d_in[0];
    const float* pos = (const float*)d_in[1];
    const float* W1 = (const float*)d_in[3];
    const float* b1 = (const float*)d_in[4];
    const float* W2 = (const float*)d_in[5];
    const float* b2 = (const float*)d_in[6];
    const float* W3 = (const float*)d_in[7];
    const float* b3 = (const float*)d_in[8];
    float* out = (float*)d_out;

    cudaFuncSetAttribute(mlp_mma_kernel, cudaFuncAttributeMaxDynamicSharedMemorySize, SMEM_TOTAL);

    fps_presplit_kernel<<<148, 512>>>(pos, x);
    ballq_kernel<<<NC/4, 128>>>(pos, out, (long long)out_size);
    mlp_mma_kernel<<<148, 512, SMEM_TOTAL>>>(pos, W1, b1, W2, b2, W3, b3, out);
}